// round 5
// baseline (speedup 1.0000x reference)
#include <cuda_runtime.h>
#include <cfloat>
#include <math.h>

#define B_  1024
#define N_  50000
#define D_  256
#define MA_ 200
#define K_  8

// ---------- device scratch (static __device__ arrays: the sanctioned way) ----------
__device__ float g_qh[B_ * D_];
__device__ float g_mh[(size_t)N_ * D_];
__device__ float g_qsq[B_];
__device__ float g_msq[N_];
__device__ float g_arg[(size_t)B_ * N_];   // ~195 MB

// ---------- packed f32x2 helpers ----------
__device__ __forceinline__ unsigned long long pk2(float x, float y) {
    unsigned long long u;
    asm("mov.b64 %0, {%1,%2};" : "=l"(u) : "f"(x), "f"(y));
    return u;
}
__device__ __forceinline__ float2 up2(unsigned long long u) {
    float2 v;
    asm("mov.b64 {%0,%1}, %2;" : "=f"(v.x), "=f"(v.y) : "l"(u));
    return v;
}
__device__ __forceinline__ void fma2(unsigned long long& c, unsigned long long a,
                                     unsigned long long b) {
    asm("fma.rn.f32x2 %0, %1, %2, %3;" : "=l"(c) : "l"(a), "l"(b), "l"(c));
}
__device__ __forceinline__ unsigned long long umin64(unsigned long long a,
                                                     unsigned long long b) {
    return a < b ? a : b;
}

// ================= kernel 1: h = tanh(X @ W + b) =================
// tile 64 rows x 128 cols, kc=32, 256 threads, 4x8 per-thread via f32x2
__global__ void __launch_bounds__(256) k_transform(const float* __restrict__ A,
                                                   const float* __restrict__ W,
                                                   const float* __restrict__ bias,
                                                   int M, int to_mem) {
    __shared__ __align__(16) float As[32][64];
    __shared__ __align__(16) float Ws[32][128];
    float* __restrict__ out = to_mem ? g_mh : g_qh;

    const int tid = threadIdx.x;
    const int rg = tid & 15;   // 16 groups x 4 rows
    const int cg = tid >> 4;   // 16 groups x 8 cols
    const int rbase = blockIdx.x * 64;
    const int cbase = blockIdx.y * 128;

    unsigned long long acc[4][4];
#pragma unroll
    for (int i = 0; i < 4; i++)
#pragma unroll
        for (int j = 0; j < 4; j++) acc[i][j] = 0ull;

    for (int ko = 0; ko < D_; ko += 32) {
        {   // A tile -> As[k][row] (transposed)
            int row = tid >> 2, ks = (tid & 3) * 8;
            int gr = rbase + row;
            float4 v0 = {0,0,0,0}, v1 = {0,0,0,0};
            if (gr < M) {
                const float4* p = reinterpret_cast<const float4*>(A + (size_t)gr * D_ + ko + ks);
                v0 = p[0]; v1 = p[1];
            }
            As[ks+0][row]=v0.x; As[ks+1][row]=v0.y; As[ks+2][row]=v0.z; As[ks+3][row]=v0.w;
            As[ks+4][row]=v1.x; As[ks+5][row]=v1.y; As[ks+6][row]=v1.z; As[ks+7][row]=v1.w;
        }
        {   // W tile natural layout Ws[k][col]
            int kk = tid >> 3, cs = (tid & 7) * 16;
            const float4* p = reinterpret_cast<const float4*>(W + (size_t)(ko + kk) * D_ + cbase + cs);
            float4 w0 = p[0], w1 = p[1], w2 = p[2], w3 = p[3];
            float4* q = reinterpret_cast<float4*>(&Ws[kk][cs]);
            q[0] = w0; q[1] = w1; q[2] = w2; q[3] = w3;
        }
        __syncthreads();
#pragma unroll
        for (int kk = 0; kk < 32; kk++) {
            float4 av = *reinterpret_cast<const float4*>(&As[kk][rg * 4]);
            float4 w0 = *reinterpret_cast<const float4*>(&Ws[kk][cg * 8]);
            float4 w1 = *reinterpret_cast<const float4*>(&Ws[kk][cg * 8 + 4]);
            unsigned long long b0 = pk2(w0.x, w0.y), b1 = pk2(w0.z, w0.w);
            unsigned long long b2 = pk2(w1.x, w1.y), b3 = pk2(w1.z, w1.w);
            unsigned long long a0 = pk2(av.x, av.x), a1 = pk2(av.y, av.y);
            unsigned long long a2 = pk2(av.z, av.z), a3 = pk2(av.w, av.w);
            fma2(acc[0][0],a0,b0); fma2(acc[0][1],a0,b1); fma2(acc[0][2],a0,b2); fma2(acc[0][3],a0,b3);
            fma2(acc[1][0],a1,b0); fma2(acc[1][1],a1,b1); fma2(acc[1][2],a1,b2); fma2(acc[1][3],a1,b3);
            fma2(acc[2][0],a2,b0); fma2(acc[2][1],a2,b1); fma2(acc[2][2],a2,b2); fma2(acc[2][3],a2,b3);
            fma2(acc[3][0],a3,b0); fma2(acc[3][1],a3,b1); fma2(acc[3][2],a3,b2); fma2(acc[3][3],a3,b3);
        }
        __syncthreads();
    }
#pragma unroll
    for (int i = 0; i < 4; i++) {
        int r = rbase + rg * 4 + i;
        if (r < M) {
#pragma unroll
            for (int j = 0; j < 4; j++) {
                float2 v = up2(acc[i][j]);
                int c = cbase + cg * 8 + j * 2;
                out[(size_t)r * D_ + c]     = tanhf(v.x + bias[c]);
                out[(size_t)r * D_ + c + 1] = tanhf(v.y + bias[c + 1]);
            }
        }
    }
}

// ================= kernel 2: Poincare rescale + row sum-of-squares =================
__global__ void k_normalize(int which) {
    float* __restrict__ h  = which ? g_mh  : g_qh;
    float* __restrict__ sq = which ? g_msq : g_qsq;
    int row = blockIdx.x, t = threadIdx.x;
    __shared__ float ws[8];
    __shared__ float br;
    size_t off = (size_t)row * D_ + t;
    float v = h[off];
    float s = v * v;
#pragma unroll
    for (int o = 16; o; o >>= 1) s += __shfl_xor_sync(0xffffffffu, s, o);
    if ((t & 31) == 0) ws[t >> 5] = s;
    __syncthreads();
    if (t == 0) {
        float tt = ws[0];
#pragma unroll
        for (int i = 1; i < 8; i++) tt += ws[i];
        br = tt;
    }
    __syncthreads();
    float norm = sqrtf(br);
    float scale = (norm > 0.95f) ? (0.95f / norm) : 1.0f;
    float y = v * scale;
    h[off] = y;
    float s2 = y * y;
#pragma unroll
    for (int o = 16; o; o >>= 1) s2 += __shfl_xor_sync(0xffffffffu, s2, o);
    __syncthreads();                 // all reads of ws/br done before reuse
    if ((t & 31) == 0) ws[t >> 5] = s2;
    __syncthreads();
    if (t == 0) {
        float tt = ws[0];
#pragma unroll
        for (int i = 1; i < 8; i++) tt += ws[i];
        sq[row] = tt;
    }
}

// ================= kernel 3: distance GEMM -> arg matrix =================
// tile 64 q x 128 m, kc=32, grid (16, ceil(N/128))
__global__ void __launch_bounds__(256) k_dist() {
    __shared__ __align__(16) float Qs[32][64];
    __shared__ __align__(16) float Ms[32][128];
    const int tid = threadIdx.x;
    const int qg = tid & 15;
    const int mg = tid >> 4;
    const int qbase = blockIdx.x * 64;
    const int mb = blockIdx.y * 128;

    unsigned long long acc[4][4];
#pragma unroll
    for (int i = 0; i < 4; i++)
#pragma unroll
        for (int j = 0; j < 4; j++) acc[i][j] = 0ull;

    for (int ko = 0; ko < D_; ko += 32) {
        {   // Q tile 64x32 transposed
            int row = tid >> 2, ks = (tid & 3) * 8;
            const float4* p = reinterpret_cast<const float4*>(g_qh + (size_t)(qbase + row) * D_ + ko + ks);
            float4 v0 = p[0], v1 = p[1];
            Qs[ks+0][row]=v0.x; Qs[ks+1][row]=v0.y; Qs[ks+2][row]=v0.z; Qs[ks+3][row]=v0.w;
            Qs[ks+4][row]=v1.x; Qs[ks+5][row]=v1.y; Qs[ks+6][row]=v1.z; Qs[ks+7][row]=v1.w;
        }
        {   // M tile 128x32 transposed
            int mrow = tid >> 1, ks = (tid & 1) * 16;
            int gm = mb + mrow;
            float4 v0={0,0,0,0}, v1={0,0,0,0}, v2={0,0,0,0}, v3={0,0,0,0};
            if (gm < N_) {
                const float4* p = reinterpret_cast<const float4*>(g_mh + (size_t)gm * D_ + ko + ks);
                v0 = p[0]; v1 = p[1]; v2 = p[2]; v3 = p[3];
            }
            Ms[ks+ 0][mrow]=v0.x; Ms[ks+ 1][mrow]=v0.y; Ms[ks+ 2][mrow]=v0.z; Ms[ks+ 3][mrow]=v0.w;
            Ms[ks+ 4][mrow]=v1.x; Ms[ks+ 5][mrow]=v1.y; Ms[ks+ 6][mrow]=v1.z; Ms[ks+ 7][mrow]=v1.w;
            Ms[ks+ 8][mrow]=v2.x; Ms[ks+ 9][mrow]=v2.y; Ms[ks+10][mrow]=v2.z; Ms[ks+11][mrow]=v2.w;
            Ms[ks+12][mrow]=v3.x; Ms[ks+13][mrow]=v3.y; Ms[ks+14][mrow]=v3.z; Ms[ks+15][mrow]=v3.w;
        }
        __syncthreads();
#pragma unroll
        for (int kk = 0; kk < 32; kk++) {
            float4 qv = *reinterpret_cast<const float4*>(&Qs[kk][qg * 4]);
            float4 m0 = *reinterpret_cast<const float4*>(&Ms[kk][mg * 8]);
            float4 m1 = *reinterpret_cast<const float4*>(&Ms[kk][mg * 8 + 4]);
            unsigned long long b0 = pk2(m0.x, m0.y), b1 = pk2(m0.z, m0.w);
            unsigned long long b2 = pk2(m1.x, m1.y), b3 = pk2(m1.z, m1.w);
            unsigned long long a0 = pk2(qv.x, qv.x), a1 = pk2(qv.y, qv.y);
            unsigned long long a2 = pk2(qv.z, qv.z), a3 = pk2(qv.w, qv.w);
            fma2(acc[0][0],a0,b0); fma2(acc[0][1],a0,b1); fma2(acc[0][2],a0,b2); fma2(acc[0][3],a0,b3);
            fma2(acc[1][0],a1,b0); fma2(acc[1][1],a1,b1); fma2(acc[1][2],a1,b2); fma2(acc[1][3],a1,b3);
            fma2(acc[2][0],a2,b0); fma2(acc[2][1],a2,b1); fma2(acc[2][2],a2,b2); fma2(acc[2][3],a2,b3);
            fma2(acc[3][0],a3,b0); fma2(acc[3][1],a3,b1); fma2(acc[3][2],a3,b2); fma2(acc[3][3],a3,b3);
        }
        __syncthreads();
    }

    // epilogue: hyperbolic arg, store
    const int gbase = mb + mg * 8;
    float msv[8];
#pragma unroll
    for (int j = 0; j < 8; j++) {
        int gm = gbase + j;
        msv[j] = (gm < N_) ? g_msq[gm] : 0.0f;
    }
#pragma unroll
    for (int i = 0; i < 4; i++) {
        int q = qbase + qg * 4 + i;
        float myq = g_qsq[q];
        float qa = 1.0f - myq;
#pragma unroll
        for (int jj = 0; jj < 4; jj++) {
            float2 d = up2(acc[i][jj]);
#pragma unroll
            for (int h = 0; h < 2; h++) {
                int j = jj * 2 + h;
                int gm = gbase + j;
                if (gm < N_) {
                    float dot = h ? d.y : d.x;
                    float diff = fmaxf(myq + msv[j] - 2.0f * dot, 0.0f);
                    float denom = qa * (1.0f - msv[j]) + 1e-8f;
                    float arg = 1.0f + (2.0f * diff) / denom;
                    g_arg[(size_t)q * N_ + gm] = arg;
                }
            }
        }
    }
}

// ================= kernel 4: per-query top-8, softmax, gather =================
__global__ void __launch_bounds__(256) k_topk(const float* __restrict__ masks,
                                              float* __restrict__ out) {
    const int q = blockIdx.x, tid = threadIdx.x;
    const float* __restrict__ row = g_arg + (size_t)q * N_;

    // per-thread sorted top-8 on key = (arg_bits << 32) | idx  (ascending arg, then idx)
    unsigned long long best[K_];
#pragma unroll
    for (int s = 0; s < K_; s++) best[s] = ~0ull;

    for (int n = tid; n < N_; n += 256) {
        float a = row[n];
        unsigned long long key = ((unsigned long long)__float_as_uint(a) << 32) | (unsigned)n;
        if (key < best[K_ - 1]) {
            best[K_ - 1] = key;
#pragma unroll
            for (int s = K_ - 1; s > 0; s--) {
                if (best[s] < best[s - 1]) {
                    unsigned long long t = best[s]; best[s] = best[s - 1]; best[s - 1] = t;
                }
            }
        }
    }

    __shared__ unsigned long long red[8];
    __shared__ unsigned long long wks;
    __shared__ float sarg[K_];
    __shared__ int sidx[K_];

    for (int s = 0; s < K_; s++) {
        unsigned long long lm = best[0];
#pragma unroll
        for (int o = 16; o; o >>= 1)
            lm = umin64(lm, __shfl_xor_sync(0xffffffffu, lm, o));
        if ((tid & 31) == 0) red[tid >> 5] = lm;
        __syncthreads();
        if (tid == 0) {
            unsigned long long m = red[0];
#pragma unroll
            for (int i = 1; i < 8; i++) m = umin64(m, red[i]);
            wks = m;
            sarg[s] = __uint_as_float((unsigned)(m >> 32));
            sidx[s] = (int)(unsigned)(m & 0xffffffffu);
        }
        __syncthreads();
        if (best[0] == wks) {   // keys are unique: exactly one owner pops
#pragma unroll
            for (int i = 0; i < K_ - 1; i++) best[i] = best[i + 1];
            best[K_ - 1] = ~0ull;
        }
        __syncthreads();
    }

    // softmax over -dist (dists ascending -> d[0] is min)
    if (tid == 0) {
        float d[K_], w[K_], sum = 0.0f;
#pragma unroll
        for (int s = 0; s < K_; s++)
            d[s] = acoshf(fmaxf(sarg[s], 1.0f + 1e-6f));
#pragma unroll
        for (int s = 0; s < K_; s++) { w[s] = expf(d[0] - d[s]); sum += w[s]; }
#pragma unroll
        for (int s = 0; s < K_; s++)
            out[(size_t)q * K_ + s] = w[s] / sum;
    }
    __syncthreads();

    // gather som_hints: out[B*K + (q*K+s)*MA + t]
    float* __restrict__ hints = out + (size_t)B_ * K_;
    for (int s = 0; s < K_; s++) {
        const float* __restrict__ src = masks + (size_t)sidx[s] * MA_;
        float* __restrict__ dst = hints + ((size_t)q * K_ + s) * MA_;
        for (int t = tid; t < MA_; t += 256) dst[t] = src[t];
    }
}

extern "C" void kernel_launch(void* const* d_in, const int* in_sizes, int n_in,
                              void* d_out, int out_size) {
    const float* q_emb  = (const float*)d_in[0];
    const float* m_emb  = (const float*)d_in[1];
    const float* masks  = (const float*)d_in[2];
    const float* W      = (const float*)d_in[3];
    const float* b      = (const float*)d_in[4];
    float* out = (float*)d_out;

    k_transform<<<dim3(B_ / 64, D_ / 128), 256>>>(q_emb, W, b, B_, 0);
    k_transform<<<dim3((N_ + 63) / 64, D_ / 128), 256>>>(m_emb, W, b, N_, 1);
    k_normalize<<<B_, 256>>>(0);
    k_normalize<<<N_, 256>>>(1);
    k_dist<<<dim3(B_ / 64, (N_ + 127) / 128), 256>>>();
    k_topk<<<B_, 256>>>(masks, out);
}